// round 6
// baseline (speedup 1.0000x reference)
#include <cuda_runtime.h>
#include <stdint.h>

// Problem-size constants (match reference: N=1e6, E=5e6, EL=2e6, D=F=16)
#define NN 1000000
#define NE 5000000
#define NEL 2000000

// ---------------------------------------------------------------------------
// Static scratch (allocation-free rule: __device__ globals)
// Feature dimension split into two 32B halves so each scatter pass's random
// working set (g-half 32MB + acc-half 32MB = 64MB) fits in the 126MB L2.
// ---------------------------------------------------------------------------
__device__ float  d_deg [NN];         // 4 MB
__device__ float  d_dinv[NN];         // 4 MB
__device__ float4 d_g0  [NN * 2];     // 32 MB : features 0..7  of g = dinv*(h@W)
__device__ float4 d_g1  [NN * 2];     // 32 MB : features 8..15
__device__ float4 d_acc0[NN * 2];     // 32 MB : accumulator half 0 (incl. self)
__device__ float4 d_acc1[NN * 2];     // 32 MB : accumulator half 1
__device__ float2 d_zfc [NN];         // 8 MB  : (z . fcw[:16], z . fcw[16:32])

// ---------------------------------------------------------------------------
// Degree
// ---------------------------------------------------------------------------
__global__ void k_deg_init(int n) {
    int i = blockIdx.x * blockDim.x + threadIdx.x;
    if (i < n) d_deg[i] = 1.0f;   // self-loop
}

__global__ void k_deg_edges(const int* __restrict__ dst, int e) {
    int i = blockIdx.x * blockDim.x + threadIdx.x;
    if (i < e) atomicAdd(&d_deg[__ldcs(dst + i)], 1.0f);
}

// ---------------------------------------------------------------------------
// Layer 1 node kernel: dinv = rsqrt(deg); h = embed[x]; g = dinv*(h@W1);
// acc = g (self-loop term)
// ---------------------------------------------------------------------------
__global__ void k_layer1(const int* __restrict__ x,
                         const float4* __restrict__ embed4,
                         const float* __restrict__ W1, int n) {
    __shared__ float Ws[256];
    int t = threadIdx.x;
    if (t < 64) ((float4*)Ws)[t] = ((const float4*)W1)[t];
    __syncthreads();

    int i = blockIdx.x * blockDim.x + t;
    if (i >= n) return;

    float dv = rsqrtf(d_deg[i]);
    d_dinv[i] = dv;

    int xi = __ldg(x + i);
    float h[16];
#pragma unroll
    for (int q = 0; q < 4; q++) {
        float4 v = embed4[(size_t)xi * 4 + q];
        h[4 * q + 0] = v.x; h[4 * q + 1] = v.y;
        h[4 * q + 2] = v.z; h[4 * q + 3] = v.w;
    }

    float acc[16];
#pragma unroll
    for (int j = 0; j < 16; j++) acc[j] = 0.0f;
#pragma unroll
    for (int k = 0; k < 16; k++) {
        float hk = h[k];
#pragma unroll
        for (int j = 0; j < 16; j++) acc[j] = fmaf(hk, Ws[k * 16 + j], acc[j]);
    }

#pragma unroll
    for (int q = 0; q < 4; q++) {
        float4 o = make_float4(dv * acc[4 * q + 0], dv * acc[4 * q + 1],
                               dv * acc[4 * q + 2], dv * acc[4 * q + 3]);
        if (q < 2) {
            d_g0  [(size_t)i * 2 + q] = o;
            d_acc0[(size_t)i * 2 + q] = o;
        } else {
            d_g1  [(size_t)i * 2 + (q - 2)] = o;
            d_acc1[(size_t)i * 2 + (q - 2)] = o;
        }
    }
}

// ---------------------------------------------------------------------------
// Edge scatter over ONE feature half: acc[dst] += g[src]  (32B per edge).
// One thread per edge: 2x LDG.128 gather + 2x red.v4.f32. Edge indices read
// with evict-first (.cs) so the 40MB stream doesn't evict the L2-resident
// tables.
// ---------------------------------------------------------------------------
__global__ void k_scatter_half(const int* __restrict__ src,
                               const int* __restrict__ dst,
                               const float4* __restrict__ g,
                               float4* __restrict__ acc, int e) {
    int i = blockIdx.x * blockDim.x + threadIdx.x;
    if (i >= e) return;
    int s  = __ldcs(src + i);
    int d0 = __ldcs(dst + i);
    float4 v0 = __ldg(g + (size_t)s * 2);
    float4 v1 = __ldg(g + (size_t)s * 2 + 1);
    float4* p = acc + (size_t)d0 * 2;
    asm volatile("red.global.add.v4.f32 [%0], {%1, %2, %3, %4};"
                 :: "l"(p), "f"(v0.x), "f"(v0.y), "f"(v0.z), "f"(v0.w)
                 : "memory");
    asm volatile("red.global.add.v4.f32 [%0], {%1, %2, %3, %4};"
                 :: "l"(p + 1), "f"(v1.x), "f"(v1.y), "f"(v1.z), "f"(v1.w)
                 : "memory");
}

// ---------------------------------------------------------------------------
// Layer 2 node kernel (fuses layer-1 epilogue):
//   h1 = relu(dinv*acc1 + b1); g2 = dinv*(h1@W2); acc2 = g2
// ---------------------------------------------------------------------------
__global__ void k_layer2(const float* __restrict__ b1,
                         const float* __restrict__ W2, int n) {
    __shared__ float Ws[256];
    __shared__ float bs[16];
    int t = threadIdx.x;
    if (t < 64) ((float4*)Ws)[t] = ((const float4*)W2)[t];
    if (t < 16) bs[t] = b1[t];
    __syncthreads();

    int i = blockIdx.x * blockDim.x + t;
    if (i >= n) return;

    float dv = d_dinv[i];
    float h[16];
#pragma unroll
    for (int q = 0; q < 4; q++) {
        float4 a = (q < 2) ? d_acc0[(size_t)i * 2 + q]
                           : d_acc1[(size_t)i * 2 + (q - 2)];
        h[4 * q + 0] = fmaxf(fmaf(dv, a.x, bs[4 * q + 0]), 0.0f);
        h[4 * q + 1] = fmaxf(fmaf(dv, a.y, bs[4 * q + 1]), 0.0f);
        h[4 * q + 2] = fmaxf(fmaf(dv, a.z, bs[4 * q + 2]), 0.0f);
        h[4 * q + 3] = fmaxf(fmaf(dv, a.w, bs[4 * q + 3]), 0.0f);
    }

    float acc[16];
#pragma unroll
    for (int j = 0; j < 16; j++) acc[j] = 0.0f;
#pragma unroll
    for (int k = 0; k < 16; k++) {
        float hk = h[k];
#pragma unroll
        for (int j = 0; j < 16; j++) acc[j] = fmaf(hk, Ws[k * 16 + j], acc[j]);
    }

#pragma unroll
    for (int q = 0; q < 4; q++) {
        float4 o = make_float4(dv * acc[4 * q + 0], dv * acc[4 * q + 1],
                               dv * acc[4 * q + 2], dv * acc[4 * q + 3]);
        if (q < 2) {
            d_g0  [(size_t)i * 2 + q] = o;
            d_acc0[(size_t)i * 2 + q] = o;
        } else {
            d_g1  [(size_t)i * 2 + (q - 2)] = o;
            d_acc1[(size_t)i * 2 + (q - 2)] = o;
        }
    }
}

// ---------------------------------------------------------------------------
// Node epilogue: z = dinv*acc2 + b2; pre-fold fc weights:
//   zfc[i] = ( z . fcw[0:16], z . fcw[16:32] )
// ---------------------------------------------------------------------------
__global__ void k_node_out(const float* __restrict__ b2,
                           const float* __restrict__ fcw, int n) {
    __shared__ float bs[16];
    __shared__ float fw[32];
    int t = threadIdx.x;
    if (t < 16) bs[t] = b2[t];
    if (t < 32) fw[t] = fcw[t];
    __syncthreads();

    int i = blockIdx.x * blockDim.x + t;
    if (i >= n) return;

    float dv = d_dinv[i];
    float s0 = 0.0f, s1 = 0.0f;
#pragma unroll
    for (int q = 0; q < 4; q++) {
        float4 a = (q < 2) ? d_acc0[(size_t)i * 2 + q]
                           : d_acc1[(size_t)i * 2 + (q - 2)];
        float z0 = fmaf(dv, a.x, bs[4 * q + 0]);
        float z1 = fmaf(dv, a.y, bs[4 * q + 1]);
        float z2 = fmaf(dv, a.z, bs[4 * q + 2]);
        float z3 = fmaf(dv, a.w, bs[4 * q + 3]);
        s0 = fmaf(z0, fw[4 * q + 0], s0);
        s0 = fmaf(z1, fw[4 * q + 1], s0);
        s0 = fmaf(z2, fw[4 * q + 2], s0);
        s0 = fmaf(z3, fw[4 * q + 3], s0);
        s1 = fmaf(z0, fw[16 + 4 * q + 0], s1);
        s1 = fmaf(z1, fw[16 + 4 * q + 1], s1);
        s1 = fmaf(z2, fw[16 + 4 * q + 2], s1);
        s1 = fmaf(z3, fw[16 + 4 * q + 3], s1);
    }
    d_zfc[i] = make_float2(s0, s1);
}

// ---------------------------------------------------------------------------
// Link prediction: out[e] = zfc[src].x + zfc[dst].y + fc_b
// ---------------------------------------------------------------------------
__global__ void k_pred(const int* __restrict__ eli,
                       float* __restrict__ out,
                       const float* __restrict__ fcb, int el) {
    int e = blockIdx.x * blockDim.x + threadIdx.x;
    if (e >= el) return;
    int s  = __ldcs(eli + e);
    int d0 = __ldcs(eli + el + e);
    float2 a = d_zfc[s];
    float2 b = d_zfc[d0];
    out[e] = a.x + b.y + __ldg(fcb);
}

// ---------------------------------------------------------------------------
// Launch
// ---------------------------------------------------------------------------
extern "C" void kernel_launch(void* const* d_in, const int* in_sizes, int n_in,
                              void* d_out, int out_size) {
    const int*   x     = (const int*)  d_in[0];
    const int*   ei    = (const int*)  d_in[1];   // [2, E]
    const int*   eli   = (const int*)  d_in[2];   // [2, EL]
    const float* embed = (const float*)d_in[3];
    const float* W1    = (const float*)d_in[4];
    const float* b1    = (const float*)d_in[5];
    const float* W2    = (const float*)d_in[6];
    const float* b2    = (const float*)d_in[7];
    const float* fcw   = (const float*)d_in[8];
    const float* fcb   = (const float*)d_in[9];
    float* out = (float*)d_out;

    int n  = in_sizes[0];
    int e  = in_sizes[1] / 2;
    int el = in_sizes[2] / 2;

    const int T = 256;
    int gn  = (n  + T - 1) / T;
    int ge  = (e  + T - 1) / T;
    int gel = (el + T - 1) / T;

    const int* src = ei;
    const int* dst = ei + e;

    float4* g0   = nullptr; cudaGetSymbolAddress((void**)&g0,   d_g0);
    float4* g1   = nullptr; cudaGetSymbolAddress((void**)&g1,   d_g1);
    float4* acc0 = nullptr; cudaGetSymbolAddress((void**)&acc0, d_acc0);
    float4* acc1 = nullptr; cudaGetSymbolAddress((void**)&acc1, d_acc1);

    k_deg_init    <<<gn, T>>>(n);
    k_deg_edges   <<<ge, T>>>(dst, e);
    k_layer1      <<<gn, T>>>(x, (const float4*)embed, W1, n);
    k_scatter_half<<<ge, T>>>(src, dst, g0, acc0, e);
    k_scatter_half<<<ge, T>>>(src, dst, g1, acc1, e);
    k_layer2      <<<gn, T>>>(b1, W2, n);
    k_scatter_half<<<ge, T>>>(src, dst, g0, acc0, e);
    k_scatter_half<<<ge, T>>>(src, dst, g1, acc1, e);
    k_node_out    <<<gn, T>>>(b2, fcw, n);
    k_pred        <<<gel, T>>>(eli, out, fcb, el);
}

// round 9
// speedup vs baseline: 1.2488x; 1.2488x over previous
#include <cuda_runtime.h>
#include <stdint.h>

// Problem-size constants (match reference: N=1e6, E=5e6, EL=2e6, D=F=16)
#define NN 1000000
#define NE 5000000
#define NEL 2000000

// ---------------------------------------------------------------------------
// Static scratch (allocation-free rule: __device__ globals)
// ---------------------------------------------------------------------------
__device__ int    d_cnt [NN];        // 4 MB  : in-degree histogram
__device__ int    d_row [NN + 1];    // 4 MB  : CSR row offsets
__device__ int    d_cur [NN];        // 4 MB  : fill cursors
__device__ int    d_csr [NE];        // 20 MB : CSR column (src) lists
__device__ int    d_bsum[1024];      //       : block sums for scan
__device__ float  d_dinv[NN];        // 4 MB
__device__ float4 d_ga  [NN * 4];    // 64 MB : layer-1 messages g1
__device__ float4 d_gb  [NN * 4];    // 64 MB : layer-2 messages g2
__device__ float2 d_zfc [NN];        // 8 MB  : (z.fcw[:16], z.fcw[16:])

// ---------------------------------------------------------------------------
// Histogram of in-degrees (also used for dinv; self-loop added later as +1)
// ---------------------------------------------------------------------------
__global__ void k_hist_init(int n) {
    int i = blockIdx.x * blockDim.x + threadIdx.x;
    if (i < n) d_cnt[i] = 0;
}

__global__ void k_hist(const int* __restrict__ dst, int e) {
    int i = blockIdx.x * blockDim.x + threadIdx.x;
    if (i < e) atomicAdd(&d_cnt[__ldcs(dst + i)], 1);
}

// ---------------------------------------------------------------------------
// Exclusive scan of d_cnt -> d_row (3 kernels; n <= 1024*1024)
// ---------------------------------------------------------------------------
__global__ void k_scanA(int n) {           // block sums (blockDim = 1024)
    __shared__ int sh[32];
    int t = threadIdx.x;
    int idx = blockIdx.x * 1024 + t;
    int v = (idx < n) ? d_cnt[idx] : 0;
#pragma unroll
    for (int o = 16; o; o >>= 1) v += __shfl_down_sync(0xffffffffu, v, o);
    if ((t & 31) == 0) sh[t >> 5] = v;
    __syncthreads();
    if (t < 32) {
        int s = sh[t];
#pragma unroll
        for (int o = 16; o; o >>= 1) s += __shfl_down_sync(0xffffffffu, s, o);
        if (t == 0) d_bsum[blockIdx.x] = s;
    }
}

__global__ void k_scanB(int nb) {          // single block: excl scan of bsums
    __shared__ int wsum[32];
    int t = threadIdx.x;
    int lane = t & 31, wid = t >> 5;
    int v = (t < nb) ? d_bsum[t] : 0;
    int x = v;
#pragma unroll
    for (int o = 1; o < 32; o <<= 1) {
        int y = __shfl_up_sync(0xffffffffu, x, o);
        if (lane >= o) x += y;
    }
    if (lane == 31) wsum[wid] = x;
    __syncthreads();
    if (wid == 0) {
        int s = wsum[lane];
#pragma unroll
        for (int o = 1; o < 32; o <<= 1) {
            int y = __shfl_up_sync(0xffffffffu, s, o);
            if (lane >= o) s += y;
        }
        wsum[lane] = s;
    }
    __syncthreads();
    int excl = x - v + (wid > 0 ? wsum[wid - 1] : 0);
    if (t < nb) d_bsum[t] = excl;
}

__global__ void k_scanC(int n) {           // per-block scan + offset -> row/cur
    __shared__ int wsum[32];
    int t = threadIdx.x;
    int lane = t & 31, wid = t >> 5;
    int idx = blockIdx.x * 1024 + t;
    int v = (idx < n) ? d_cnt[idx] : 0;
    int x = v;
#pragma unroll
    for (int o = 1; o < 32; o <<= 1) {
        int y = __shfl_up_sync(0xffffffffu, x, o);
        if (lane >= o) x += y;
    }
    if (lane == 31) wsum[wid] = x;
    __syncthreads();
    if (wid == 0) {
        int s = wsum[lane];
#pragma unroll
        for (int o = 1; o < 32; o <<= 1) {
            int y = __shfl_up_sync(0xffffffffu, s, o);
            if (lane >= o) s += y;
        }
        wsum[lane] = s;
    }
    __syncthreads();
    int excl = x - v + (wid > 0 ? wsum[wid - 1] : 0);
    if (idx < n) {
        int r = d_bsum[blockIdx.x] + excl;
        d_row[idx] = r;
        d_cur[idx] = r;
        if (idx == n - 1) d_row[n] = r + v;
    }
}

// ---------------------------------------------------------------------------
// CSR fill: csr[cursor[dst]++] = src
// ---------------------------------------------------------------------------
__global__ void k_fill(const int* __restrict__ src,
                       const int* __restrict__ dst, int e) {
    int i = blockIdx.x * blockDim.x + threadIdx.x;
    if (i >= e) return;
    int s  = __ldcs(src + i);
    int d0 = __ldcs(dst + i);
    int pos = atomicAdd(&d_cur[d0], 1);
    d_csr[pos] = s;
}

// ---------------------------------------------------------------------------
// Layer-1 node kernel: dinv = rsqrt(deg+1); g1 = dinv*(embed[x]@W1)
// ---------------------------------------------------------------------------
__global__ void k_layer1(const int* __restrict__ x,
                         const float4* __restrict__ embed4,
                         const float* __restrict__ W1, int n) {
    __shared__ float Ws[256];
    int t = threadIdx.x;
    if (t < 64) ((float4*)Ws)[t] = ((const float4*)W1)[t];
    __syncthreads();

    int i = blockIdx.x * blockDim.x + t;
    if (i >= n) return;

    float dv = rsqrtf((float)(d_cnt[i] + 1));   // +1 self-loop
    d_dinv[i] = dv;

    int xi = __ldg(x + i);
    float h[16];
#pragma unroll
    for (int q = 0; q < 4; q++) {
        float4 v = embed4[(size_t)xi * 4 + q];
        h[4 * q + 0] = v.x; h[4 * q + 1] = v.y;
        h[4 * q + 2] = v.z; h[4 * q + 3] = v.w;
    }

    float acc[16];
#pragma unroll
    for (int j = 0; j < 16; j++) acc[j] = 0.0f;
#pragma unroll
    for (int k = 0; k < 16; k++) {
        float hk = h[k];
#pragma unroll
        for (int j = 0; j < 16; j++) acc[j] = fmaf(hk, Ws[k * 16 + j], acc[j]);
    }

#pragma unroll
    for (int q = 0; q < 4; q++)
        d_ga[(size_t)i * 4 + q] =
            make_float4(dv * acc[4 * q + 0], dv * acc[4 * q + 1],
                        dv * acc[4 * q + 2], dv * acc[4 * q + 3]);
}

// ---------------------------------------------------------------------------
// Gather layer 1 -> 2 (fused epilogue + next GEMM):
//   sum = g1[i] + sum_{j in N(i)} g1[j]
//   h1  = relu(dinv*sum + b1);  g2 = dinv*(h1@W2)   (streamed out, .cs)
// ---------------------------------------------------------------------------
__global__ void k_gather1(const float* __restrict__ b1,
                          const float* __restrict__ W2, int n) {
    __shared__ float Ws[256];
    __shared__ float bs[16];
    int t = threadIdx.x;
    if (t < 64) ((float4*)Ws)[t] = ((const float4*)W2)[t];
    if (t < 16) bs[t] = b1[t];
    __syncthreads();

    int i = blockIdx.x * blockDim.x + t;
    if (i >= n) return;

    size_t o = (size_t)i * 4;
    float4 a0 = d_ga[o + 0], a1 = d_ga[o + 1];
    float4 a2 = d_ga[o + 2], a3 = d_ga[o + 3];

    int beg = d_row[i], end = d_row[i + 1];
    for (int j = beg; j < end; j++) {
        size_t so = (size_t)__ldg(d_csr + j) * 4;
        float4 v0 = __ldg(&d_ga[so + 0]);
        float4 v1 = __ldg(&d_ga[so + 1]);
        float4 v2 = __ldg(&d_ga[so + 2]);
        float4 v3 = __ldg(&d_ga[so + 3]);
        a0.x += v0.x; a0.y += v0.y; a0.z += v0.z; a0.w += v0.w;
        a1.x += v1.x; a1.y += v1.y; a1.z += v1.z; a1.w += v1.w;
        a2.x += v2.x; a2.y += v2.y; a2.z += v2.z; a2.w += v2.w;
        a3.x += v3.x; a3.y += v3.y; a3.z += v3.z; a3.w += v3.w;
    }

    float dv = d_dinv[i];
    float h[16];
    h[0]  = fmaxf(fmaf(dv, a0.x, bs[0]),  0.0f);
    h[1]  = fmaxf(fmaf(dv, a0.y, bs[1]),  0.0f);
    h[2]  = fmaxf(fmaf(dv, a0.z, bs[2]),  0.0f);
    h[3]  = fmaxf(fmaf(dv, a0.w, bs[3]),  0.0f);
    h[4]  = fmaxf(fmaf(dv, a1.x, bs[4]),  0.0f);
    h[5]  = fmaxf(fmaf(dv, a1.y, bs[5]),  0.0f);
    h[6]  = fmaxf(fmaf(dv, a1.z, bs[6]),  0.0f);
    h[7]  = fmaxf(fmaf(dv, a1.w, bs[7]),  0.0f);
    h[8]  = fmaxf(fmaf(dv, a2.x, bs[8]),  0.0f);
    h[9]  = fmaxf(fmaf(dv, a2.y, bs[9]),  0.0f);
    h[10] = fmaxf(fmaf(dv, a2.z, bs[10]), 0.0f);
    h[11] = fmaxf(fmaf(dv, a2.w, bs[11]), 0.0f);
    h[12] = fmaxf(fmaf(dv, a3.x, bs[12]), 0.0f);
    h[13] = fmaxf(fmaf(dv, a3.y, bs[13]), 0.0f);
    h[14] = fmaxf(fmaf(dv, a3.z, bs[14]), 0.0f);
    h[15] = fmaxf(fmaf(dv, a3.w, bs[15]), 0.0f);

    float acc[16];
#pragma unroll
    for (int j = 0; j < 16; j++) acc[j] = 0.0f;
#pragma unroll
    for (int k = 0; k < 16; k++) {
        float hk = h[k];
#pragma unroll
        for (int j = 0; j < 16; j++) acc[j] = fmaf(hk, Ws[k * 16 + j], acc[j]);
    }

#pragma unroll
    for (int q = 0; q < 4; q++)
        __stcs(&d_gb[o + q],
               make_float4(dv * acc[4 * q + 0], dv * acc[4 * q + 1],
                           dv * acc[4 * q + 2], dv * acc[4 * q + 3]));
}

// ---------------------------------------------------------------------------
// Gather layer 2 (fused fc fold):
//   sum = g2[i] + sum_{j in N(i)} g2[j];  z = dinv*sum + b2
//   zfc = (z . fcw[0:16], z . fcw[16:32])
// ---------------------------------------------------------------------------
__global__ void k_gather2(const float* __restrict__ b2,
                          const float* __restrict__ fcw, int n) {
    __shared__ float bs[16];
    __shared__ float fw[32];
    int t = threadIdx.x;
    if (t < 16) bs[t] = b2[t];
    if (t < 32) fw[t] = fcw[t];
    __syncthreads();

    int i = blockIdx.x * blockDim.x + t;
    if (i >= n) return;

    size_t o = (size_t)i * 4;
    float4 a0 = d_gb[o + 0], a1 = d_gb[o + 1];
    float4 a2 = d_gb[o + 2], a3 = d_gb[o + 3];

    int beg = d_row[i], end = d_row[i + 1];
    for (int j = beg; j < end; j++) {
        size_t so = (size_t)__ldg(d_csr + j) * 4;
        float4 v0 = __ldg(&d_gb[so + 0]);
        float4 v1 = __ldg(&d_gb[so + 1]);
        float4 v2 = __ldg(&d_gb[so + 2]);
        float4 v3 = __ldg(&d_gb[so + 3]);
        a0.x += v0.x; a0.y += v0.y; a0.z += v0.z; a0.w += v0.w;
        a1.x += v1.x; a1.y += v1.y; a1.z += v1.z; a1.w += v1.w;
        a2.x += v2.x; a2.y += v2.y; a2.z += v2.z; a2.w += v2.w;
        a3.x += v3.x; a3.y += v3.y; a3.z += v3.z; a3.w += v3.w;
    }

    float dv = d_dinv[i];
    float z[16];
    z[0]  = fmaf(dv, a0.x, bs[0]);  z[1]  = fmaf(dv, a0.y, bs[1]);
    z[2]  = fmaf(dv, a0.z, bs[2]);  z[3]  = fmaf(dv, a0.w, bs[3]);
    z[4]  = fmaf(dv, a1.x, bs[4]);  z[5]  = fmaf(dv, a1.y, bs[5]);
    z[6]  = fmaf(dv, a1.z, bs[6]);  z[7]  = fmaf(dv, a1.w, bs[7]);
    z[8]  = fmaf(dv, a2.x, bs[8]);  z[9]  = fmaf(dv, a2.y, bs[9]);
    z[10] = fmaf(dv, a2.z, bs[10]); z[11] = fmaf(dv, a2.w, bs[11]);
    z[12] = fmaf(dv, a3.x, bs[12]); z[13] = fmaf(dv, a3.y, bs[13]);
    z[14] = fmaf(dv, a3.z, bs[14]); z[15] = fmaf(dv, a3.w, bs[15]);

    float s0 = 0.0f, s1 = 0.0f;
#pragma unroll
    for (int k = 0; k < 16; k++) {
        s0 = fmaf(z[k], fw[k], s0);
        s1 = fmaf(z[k], fw[16 + k], s1);
    }
    d_zfc[i] = make_float2(s0, s1);
}

// ---------------------------------------------------------------------------
// Link prediction: out[e] = zfc[src].x + zfc[dst].y + fc_b
// ---------------------------------------------------------------------------
__global__ void k_pred(const int* __restrict__ eli,
                       float* __restrict__ out,
                       const float* __restrict__ fcb, int el) {
    int e = blockIdx.x * blockDim.x + threadIdx.x;
    if (e >= el) return;
    int s  = __ldcs(eli + e);
    int d0 = __ldcs(eli + el + e);
    float2 a = d_zfc[s];
    float2 b = d_zfc[d0];
    out[e] = a.x + b.y + __ldg(fcb);
}

// ---------------------------------------------------------------------------
// Launch
// ---------------------------------------------------------------------------
extern "C" void kernel_launch(void* const* d_in, const int* in_sizes, int n_in,
                              void* d_out, int out_size) {
    const int*   x     = (const int*)  d_in[0];
    const int*   ei    = (const int*)  d_in[1];   // [2, E]
    const int*   eli   = (const int*)  d_in[2];   // [2, EL]
    const float* embed = (const float*)d_in[3];
    const float* W1    = (const float*)d_in[4];
    const float* b1    = (const float*)d_in[5];
    const float* W2    = (const float*)d_in[6];
    const float* b2    = (const float*)d_in[7];
    const float* fcw   = (const float*)d_in[8];
    const float* fcb   = (const float*)d_in[9];
    float* out = (float*)d_out;

    int n  = in_sizes[0];
    int e  = in_sizes[1] / 2;
    int el = in_sizes[2] / 2;

    const int T = 256;
    int gn  = (n  + T - 1) / T;
    int ge  = (e  + T - 1) / T;
    int gel = (el + T - 1) / T;
    int gsc = (n + 1023) / 1024;      // scan blocks (<= 1024 required)

    const int* src = ei;
    const int* dst = ei + e;

    k_hist_init<<<gn,  T>>>(n);
    k_hist     <<<ge,  T>>>(dst, e);
    k_scanA    <<<gsc, 1024>>>(n);
    k_scanB    <<<1,   1024>>>(gsc);
    k_scanC    <<<gsc, 1024>>>(n);
    k_fill     <<<ge,  T>>>(src, dst, e);
    k_layer1   <<<gn,  T>>>(x, (const float4*)embed, W1, n);
    k_gather1  <<<gn,  T>>>(b1, W2, n);
    k_gather2  <<<gn,  T>>>(b2, fcw, n);
    k_pred     <<<gel, T>>>(eli, out, fcb, el);
}

// round 12
// speedup vs baseline: 1.2518x; 1.0024x over previous
#include <cuda_runtime.h>
#include <stdint.h>

// Problem-size constants (match reference: N=1e6, E=5e6, EL=2e6, D=F=16)
#define NN 1000000
#define NE 5000000
#define NEL 2000000

// ---------------------------------------------------------------------------
// Static scratch (allocation-free rule: __device__ globals)
// ---------------------------------------------------------------------------
__device__ int    d_cnt [NN];        // 4 MB  : in-degree histogram
__device__ int    d_row [NN + 1];    // 4 MB  : CSR row offsets
__device__ int    d_cur [NN];        // 4 MB  : fill cursors
__device__ int    d_csr [NE];        // 20 MB : CSR column (src) lists
__device__ int    d_bsum[1024];      //       : block sums for scan
__device__ float  d_dinv[NN];        // 4 MB
__device__ float4 d_ga  [NN * 4];    // 64 MB : layer-1 messages g1
__device__ float4 d_gb  [NN * 4];    // 64 MB : layer-2 messages g2
__device__ float2 d_zfc [NN];        // 8 MB  : (z.fcw[:16], z.fcw[16:]+fcb)

// ---------------------------------------------------------------------------
// Histogram of in-degrees (d_cnt zeroed by cudaMemsetAsync before this)
// ---------------------------------------------------------------------------
__global__ void k_hist(const int* __restrict__ dst, int e) {
    int i = blockIdx.x * blockDim.x + threadIdx.x;
    if (i < e) atomicAdd(&d_cnt[__ldcs(dst + i)], 1);
}

// ---------------------------------------------------------------------------
// Exclusive scan of d_cnt -> d_row, 4 elements per thread (n % 4 == 0).
// Block = 1024 threads = 4096 elements. n=1e6 -> 245 blocks, bsum fits 1024.
// ---------------------------------------------------------------------------
__global__ void k_scanA(int n4) {          // block sums over int4 elements
    __shared__ int sh[32];
    int t = threadIdx.x;
    int i4 = blockIdx.x * 1024 + t;
    int v = 0;
    if (i4 < n4) {
        int4 c = ((const int4*)d_cnt)[i4];
        v = c.x + c.y + c.z + c.w;
    }
#pragma unroll
    for (int o = 16; o; o >>= 1) v += __shfl_down_sync(0xffffffffu, v, o);
    if ((t & 31) == 0) sh[t >> 5] = v;
    __syncthreads();
    if (t < 32) {
        int s = sh[t];
#pragma unroll
        for (int o = 16; o; o >>= 1) s += __shfl_down_sync(0xffffffffu, s, o);
        if (t == 0) d_bsum[blockIdx.x] = s;
    }
}

__global__ void k_scanB(int nb) {          // single block: excl scan of bsums
    __shared__ int wsum[32];
    int t = threadIdx.x;
    int lane = t & 31, wid = t >> 5;
    int v = (t < nb) ? d_bsum[t] : 0;
    int x = v;
#pragma unroll
    for (int o = 1; o < 32; o <<= 1) {
        int y = __shfl_up_sync(0xffffffffu, x, o);
        if (lane >= o) x += y;
    }
    if (lane == 31) wsum[wid] = x;
    __syncthreads();
    if (wid == 0) {
        int s = wsum[lane];
#pragma unroll
        for (int o = 1; o < 32; o <<= 1) {
            int y = __shfl_up_sync(0xffffffffu, s, o);
            if (lane >= o) s += y;
        }
        wsum[lane] = s;
    }
    __syncthreads();
    int excl = x - v + (wid > 0 ? wsum[wid - 1] : 0);
    if (t < nb) d_bsum[t] = excl;
}

__global__ void k_scanC(int n4, int n) {   // full scan -> d_row, d_cur
    __shared__ int wsum[32];
    int t = threadIdx.x;
    int lane = t & 31, wid = t >> 5;
    int i4 = blockIdx.x * 1024 + t;
    int4 c = make_int4(0, 0, 0, 0);
    if (i4 < n4) c = ((const int4*)d_cnt)[i4];
    int v = c.x + c.y + c.z + c.w;
    int x = v;
#pragma unroll
    for (int o = 1; o < 32; o <<= 1) {
        int y = __shfl_up_sync(0xffffffffu, x, o);
        if (lane >= o) x += y;
    }
    if (lane == 31) wsum[wid] = x;
    __syncthreads();
    if (wid == 0) {
        int s = wsum[lane];
#pragma unroll
        for (int o = 1; o < 32; o <<= 1) {
            int y = __shfl_up_sync(0xffffffffu, s, o);
            if (lane >= o) s += y;
        }
        wsum[lane] = s;
    }
    __syncthreads();
    int excl = x - v + (wid > 0 ? wsum[wid - 1] : 0);
    if (i4 < n4) {
        int r0 = d_bsum[blockIdx.x] + excl;
        int r1 = r0 + c.x;
        int r2 = r1 + c.y;
        int r3 = r2 + c.z;
        int4 rv = make_int4(r0, r1, r2, r3);
        ((int4*)d_row)[i4] = rv;
        ((int4*)d_cur)[i4] = rv;
        if (i4 == n4 - 1) d_row[n] = r3 + c.w;
    }
}

// ---------------------------------------------------------------------------
// CSR fill: csr[cursor[dst]++] = src
// ---------------------------------------------------------------------------
__global__ void k_fill(const int* __restrict__ src,
                       const int* __restrict__ dst, int e) {
    int i = blockIdx.x * blockDim.x + threadIdx.x;
    if (i >= e) return;
    int s  = __ldcs(src + i);
    int d0 = __ldcs(dst + i);
    int pos = atomicAdd(&d_cur[d0], 1);
    d_csr[pos] = s;
}

// ---------------------------------------------------------------------------
// Layer-1 node kernel: dinv = rsqrt(deg+1); g1 = dinv*(embed[x]@W1)
// ---------------------------------------------------------------------------
__global__ void k_layer1(const int* __restrict__ x,
                         const float4* __restrict__ embed4,
                         const float* __restrict__ W1, int n) {
    __shared__ float Ws[256];
    int t = threadIdx.x;
    if (t < 64) ((float4*)Ws)[t] = ((const float4*)W1)[t];
    __syncthreads();

    int i = blockIdx.x * blockDim.x + t;
    if (i >= n) return;

    float dv = rsqrtf((float)(d_cnt[i] + 1));   // +1 self-loop
    d_dinv[i] = dv;

    int xi = __ldg(x + i);
    float h[16];
#pragma unroll
    for (int q = 0; q < 4; q++) {
        float4 v = embed4[(size_t)xi * 4 + q];
        h[4 * q + 0] = v.x; h[4 * q + 1] = v.y;
        h[4 * q + 2] = v.z; h[4 * q + 3] = v.w;
    }

    float acc[16];
#pragma unroll
    for (int j = 0; j < 16; j++) acc[j] = 0.0f;
#pragma unroll
    for (int k = 0; k < 16; k++) {
        float hk = h[k];
#pragma unroll
        for (int j = 0; j < 16; j++) acc[j] = fmaf(hk, Ws[k * 16 + j], acc[j]);
    }

#pragma unroll
    for (int q = 0; q < 4; q++)
        d_ga[(size_t)i * 4 + q] =
            make_float4(dv * acc[4 * q + 0], dv * acc[4 * q + 1],
                        dv * acc[4 * q + 2], dv * acc[4 * q + 3]);
}

// ---------------------------------------------------------------------------
// Neighbor-sum helper: 2-edge unrolled gather loop (8 LDG.128 in flight).
// Accumulation order per feature register is preserved (j ascending).
// ---------------------------------------------------------------------------
__device__ __forceinline__ void gather_sum(const float4* __restrict__ tab,
                                           int beg, int end,
                                           float4& a0, float4& a1,
                                           float4& a2, float4& a3) {
    int j = beg;
    for (; j + 1 < end; j += 2) {
        size_t sa = (size_t)__ldg(d_csr + j)     * 4;
        size_t sb = (size_t)__ldg(d_csr + j + 1) * 4;
        float4 p0 = __ldg(tab + sa + 0);
        float4 p1 = __ldg(tab + sa + 1);
        float4 p2 = __ldg(tab + sa + 2);
        float4 p3 = __ldg(tab + sa + 3);
        float4 q0 = __ldg(tab + sb + 0);
        float4 q1 = __ldg(tab + sb + 1);
        float4 q2 = __ldg(tab + sb + 2);
        float4 q3 = __ldg(tab + sb + 3);
        a0.x += p0.x; a0.y += p0.y; a0.z += p0.z; a0.w += p0.w;
        a1.x += p1.x; a1.y += p1.y; a1.z += p1.z; a1.w += p1.w;
        a2.x += p2.x; a2.y += p2.y; a2.z += p2.z; a2.w += p2.w;
        a3.x += p3.x; a3.y += p3.y; a3.z += p3.z; a3.w += p3.w;
        a0.x += q0.x; a0.y += q0.y; a0.z += q0.z; a0.w += q0.w;
        a1.x += q1.x; a1.y += q1.y; a1.z += q1.z; a1.w += q1.w;
        a2.x += q2.x; a2.y += q2.y; a2.z += q2.z; a2.w += q2.w;
        a3.x += q3.x; a3.y += q3.y; a3.z += q3.z; a3.w += q3.w;
    }
    if (j < end) {
        size_t sa = (size_t)__ldg(d_csr + j) * 4;
        float4 p0 = __ldg(tab + sa + 0);
        float4 p1 = __ldg(tab + sa + 1);
        float4 p2 = __ldg(tab + sa + 2);
        float4 p3 = __ldg(tab + sa + 3);
        a0.x += p0.x; a0.y += p0.y; a0.z += p0.z; a0.w += p0.w;
        a1.x += p1.x; a1.y += p1.y; a1.z += p1.z; a1.w += p1.w;
        a2.x += p2.x; a2.y += p2.y; a2.z += p2.z; a2.w += p2.w;
        a3.x += p3.x; a3.y += p3.y; a3.z += p3.z; a3.w += p3.w;
    }
}

// ---------------------------------------------------------------------------
// Gather layer 1 -> 2 (fused epilogue + next GEMM):
//   sum = g1[i] + sum_{j in N(i)} g1[j]
//   h1  = relu(dinv*sum + b1);  g2 = dinv*(h1@W2)   (streamed out, .cs)
// ---------------------------------------------------------------------------
__global__ void k_gather1(const float* __restrict__ b1,
                          const float* __restrict__ W2, int n) {
    __shared__ float Ws[256];
    __shared__ float bs[16];
    int t = threadIdx.x;
    if (t < 64) ((float4*)Ws)[t] = ((const float4*)W2)[t];
    if (t < 16) bs[t] = b1[t];
    __syncthreads();

    int i = blockIdx.x * blockDim.x + t;
    if (i >= n) return;

    size_t o = (size_t)i * 4;
    float4 a0 = d_ga[o + 0], a1 = d_ga[o + 1];
    float4 a2 = d_ga[o + 2], a3 = d_ga[o + 3];

    gather_sum(d_ga, d_row[i], d_row[i + 1], a0, a1, a2, a3);

    float dv = d_dinv[i];
    float h[16];
    h[0]  = fmaxf(fmaf(dv, a0.x, bs[0]),  0.0f);
    h[1]  = fmaxf(fmaf(dv, a0.y, bs[1]),  0.0f);
    h[2]  = fmaxf(fmaf(dv, a0.z, bs[2]),  0.0f);
    h[3]  = fmaxf(fmaf(dv, a0.w, bs[3]),  0.0f);
    h[4]  = fmaxf(fmaf(dv, a1.x, bs[4]),  0.0f);
    h[5]  = fmaxf(fmaf(dv, a1.y, bs[5]),  0.0f);
    h[6]  = fmaxf(fmaf(dv, a1.z, bs[6]),  0.0f);
    h[7]  = fmaxf(fmaf(dv, a1.w, bs[7]),  0.0f);
    h[8]  = fmaxf(fmaf(dv, a2.x, bs[8]),  0.0f);
    h[9]  = fmaxf(fmaf(dv, a2.y, bs[9]),  0.0f);
    h[10] = fmaxf(fmaf(dv, a2.z, bs[10]), 0.0f);
    h[11] = fmaxf(fmaf(dv, a2.w, bs[11]), 0.0f);
    h[12] = fmaxf(fmaf(dv, a3.x, bs[12]), 0.0f);
    h[13] = fmaxf(fmaf(dv, a3.y, bs[13]), 0.0f);
    h[14] = fmaxf(fmaf(dv, a3.z, bs[14]), 0.0f);
    h[15] = fmaxf(fmaf(dv, a3.w, bs[15]), 0.0f);

    float acc[16];
#pragma unroll
    for (int j = 0; j < 16; j++) acc[j] = 0.0f;
#pragma unroll
    for (int k = 0; k < 16; k++) {
        float hk = h[k];
#pragma unroll
        for (int j = 0; j < 16; j++) acc[j] = fmaf(hk, Ws[k * 16 + j], acc[j]);
    }

#pragma unroll
    for (int q = 0; q < 4; q++)
        __stcs(&d_gb[o + q],
               make_float4(dv * acc[4 * q + 0], dv * acc[4 * q + 1],
                           dv * acc[4 * q + 2], dv * acc[4 * q + 3]));
}

// ---------------------------------------------------------------------------
// Gather layer 2 (fused fc fold):
//   sum = g2[i] + sum_{j in N(i)} g2[j];  z = dinv*sum + b2
//   zfc = (z . fcw[0:16], z . fcw[16:32] + fcb)
// ---------------------------------------------------------------------------
__global__ void k_gather2(const float* __restrict__ b2,
                          const float* __restrict__ fcw,
                          const float* __restrict__ fcb, int n) {
    __shared__ float bs[16];
    __shared__ float fw[32];
    int t = threadIdx.x;
    if (t < 16) bs[t] = b2[t];
    if (t < 32) fw[t] = fcw[t];
    __syncthreads();

    int i = blockIdx.x * blockDim.x + t;
    if (i >= n) return;

    size_t o = (size_t)i * 4;
    float4 a0 = d_gb[o + 0], a1 = d_gb[o + 1];
    float4 a2 = d_gb[o + 2], a3 = d_gb[o + 3];

    gather_sum(d_gb, d_row[i], d_row[i + 1], a0, a1, a2, a3);

    float dv = d_dinv[i];
    float z[16];
    z[0]  = fmaf(dv, a0.x, bs[0]);  z[1]  = fmaf(dv, a0.y, bs[1]);
    z[2]  = fmaf(dv, a0.z, bs[2]);  z[3]  = fmaf(dv, a0.w, bs[3]);
    z[4]  = fmaf(dv, a1.x, bs[4]);  z[5]  = fmaf(dv, a1.y, bs[5]);
    z[6]  = fmaf(dv, a1.z, bs[6]);  z[7]  = fmaf(dv, a1.w, bs[7]);
    z[8]  = fmaf(dv, a2.x, bs[8]);  z[9]  = fmaf(dv, a2.y, bs[9]);
    z[10] = fmaf(dv, a2.z, bs[10]); z[11] = fmaf(dv, a2.w, bs[11]);
    z[12] = fmaf(dv, a3.x, bs[12]); z[13] = fmaf(dv, a3.y, bs[13]);
    z[14] = fmaf(dv, a3.z, bs[14]); z[15] = fmaf(dv, a3.w, bs[15]);

    float s0 = 0.0f, s1 = __ldg(fcb);
#pragma unroll
    for (int k = 0; k < 16; k++) {
        s0 = fmaf(z[k], fw[k], s0);
        s1 = fmaf(z[k], fw[16 + k], s1);
    }
    d_zfc[i] = make_float2(s0, s1);
}

// ---------------------------------------------------------------------------
// Link prediction: out[e] = zfc[src].x + zfc[dst].y   (fcb pre-folded)
// ---------------------------------------------------------------------------
__global__ void k_pred(const int* __restrict__ eli,
                       float* __restrict__ out, int el) {
    int e = blockIdx.x * blockDim.x + threadIdx.x;
    if (e >= el) return;
    int s  = __ldcs(eli + e);
    int d0 = __ldcs(eli + el + e);
    float2 a = d_zfc[s];
    float2 b = d_zfc[d0];
    out[e] = a.x + b.y;
}

// ---------------------------------------------------------------------------
// Launch
// ---------------------------------------------------------------------------
extern "C" void kernel_launch(void* const* d_in, const int* in_sizes, int n_in,
                              void* d_out, int out_size) {
    const int*   x     = (const int*)  d_in[0];
    const int*   ei    = (const int*)  d_in[1];   // [2, E]
    const int*   eli   = (const int*)  d_in[2];   // [2, EL]
    const float* embed = (const float*)d_in[3];
    const float* W1    = (const float*)d_in[4];
    const float* b1    = (const float*)d_in[5];
    const float* W2    = (const float*)d_in[6];
    const float* b2    = (const float*)d_in[7];
    const float* fcw   = (const float*)d_in[8];
    const float* fcb   = (const float*)d_in[9];
    float* out = (float*)d_out;

    int n  = in_sizes[0];
    int e  = in_sizes[1] / 2;
    int el = in_sizes[2] / 2;
    int n4 = n / 4;                    // N = 1e6, divisible by 4

    const int T = 256;
    int gn  = (n  + T - 1) / T;
    int ge  = (e  + T - 1) / T;
    int gel = (el + T - 1) / T;
    int gsc = (n4 + 1023) / 1024;      // 245 blocks (<= 1024 for scanB)

    const int* src = ei;
    const int* dst = ei + e;

    void* cnt_ptr = nullptr;
    cudaGetSymbolAddress(&cnt_ptr, d_cnt);

    cudaMemsetAsync(cnt_ptr, 0, (size_t)n * sizeof(int));
    k_hist   <<<ge,  T>>>(dst, e);
    k_scanA  <<<gsc, 1024>>>(n4);
    k_scanB  <<<1,   1024>>>(gsc);
    k_scanC  <<<gsc, 1024>>>(n4, n);
    k_fill   <<<ge,  T>>>(src, dst, e);
    k_layer1 <<<gn,  T>>>(x, (const float4*)embed, W1, n);
    k_gather1<<<gn,  T>>>(b1, W2, n);
    k_gather2<<<gn,  T>>>(b2, fcw, fcb, n);
    k_pred   <<<gel, T>>>(eli, out, el);
}